// round 12
// baseline (speedup 1.0000x reference)
#include <cuda_runtime.h>
#include <string.h>

// Per-channel 5x5 correlation, stride=1, pad=2; 128 planes of 512x512 f32.
// Register-rolling accumulation + cp.async smem row ring (R11 base), plus:
//   - cp.async.cg (L1-bypass) row staging: staged rows are only read back
//     through smem, so L1 caching of them was pure l1tex overhead.
//   - streaming output stores (st.global.cs): write-once data evicts first,
//     preserving input halo rows in L2 for the adjacent strips.
//   - 2-warp CTAs (block 64): finer wave granularity (4096 CTAs) and a
//     higher warp cap (13 CTAs -> 26 warps/SM at 76 regs).
//   - partial prologue/epilogue accsteps (1600 FMA2/strip), depth-4 prefetch.

#define IMG   512
#define R     16
#define NSTEP (R + 4)          // 20 input rows per strip
#define ROWB  1056             // 264 floats per staged row
#define RING  5
#define WSM   (RING * ROWB)    // 5280 B per warp

typedef unsigned long long u64;

__device__ __forceinline__ u64 pk(float lo, float hi) {
    float2 t; t.x = lo; t.y = hi;
    u64 r; memcpy(&r, &t, 8);
    return r;
}
__device__ __forceinline__ u64 pk2(float2 t) {
    u64 r; memcpy(&r, &t, 8);
    return r;
}
__device__ __forceinline__ u64 fma2(u64 a, u64 b, u64 c) {
    u64 d;
    asm("fma.rn.f32x2 %0, %1, %2, %3;" : "=l"(d) : "l"(a), "l"(b), "l"(c));
    return d;
}
__device__ __forceinline__ u64 mul2(u64 a, u64 b) {
    u64 d;
    asm("mul.rn.f32x2 %0, %1, %2;" : "=l"(d) : "l"(a), "l"(b));
    return d;
}
__device__ __forceinline__ void cpa16(unsigned d, const void* g) {
    asm volatile("cp.async.cg.shared.global [%0], [%1], 16;" :: "r"(d), "l"(g));
}
__device__ __forceinline__ void stsz(unsigned a) {
    asm volatile("st.shared.v4.u32 [%0], {%1,%1,%1,%1};" :: "r"(a), "r"(0u));
}
__device__ __forceinline__ void stg_cs(float* p, u64 a, u64 b) {
    asm volatile("st.global.cs.v2.b64 [%0], {%1, %2};" :: "l"(p), "l"(a), "l"(b));
}

// Taps of input-row s (I = s mod 5) into pending output slots, restricted to
// kernel rows kr in [KRLO, KRHI]. Output o = s - kr lives in slot o % 5.
// kr==0 is an output's chronologically FIRST contribution: overwrite via mul.
template<int I, int KRLO, int KRHI>
__device__ __forceinline__ void accstep(u64 acc[5][4],
                                        const u64* __restrict__ wp,
                                        const u64* __restrict__ p) {
    #pragma unroll
    for (int kr = KRLO; kr <= KRHI; kr++) {
        const int slot = ((I - kr) % 5 + 5) % 5;
        #pragma unroll
        for (int t = 0; t < 5; t++) {
            #pragma unroll
            for (int pj = 0; pj < 4; pj++) {
                if (kr == 0 && t == 0)
                    acc[slot][pj] = mul2(wp[0], p[2 * pj]);
                else
                    acc[slot][pj] = fma2(wp[kr * 5 + t], p[2 * pj + t], acc[slot][pj]);
            }
        }
    }
}

__global__ __launch_bounds__(64, 12) void conv5x5_kernel(
    const float* __restrict__ X,
    const float* __restrict__ Kw,
    float* __restrict__ Out)
{
    __shared__ __align__(16) char ring[2 * WSM];

    const int lane  = threadIdx.x;
    const int wrp   = threadIdx.y;                  // 0..1
    const int c     = blockIdx.z;
    const int warpX = blockIdx.x;                   // 0..1
    const int strip = blockIdx.y * 2 + wrp;         // 0..31
    const int Y0    = strip * R;
    const int x0w   = warpX * 256;                  // warp x base
    const int x0    = x0w + lane * 8;               // lane x base

    const float* __restrict__ Xc = X   + (size_t)c * (IMG * IMG);
    float*       __restrict__ Oc = Out + (size_t)c * (IMG * IMG);

    const char* wring = ring + wrp * WSM;                       // generic, for LDS
    const unsigned sbase =
        (unsigned)__cvta_generic_to_shared(ring) + wrp * WSM;   // for cp.async/STS

    // zero the permanently-out-of-image x-edge chunk of every ring slot ONCE:
    // chunk 0 (x0w-4..-1) for warpX==0, chunk 65 (x 512..515) for warpX==1.
    if (lane < RING)
        stsz(sbase + lane * ROWB + (warpX ? 65 * 16 : 0));
    __syncwarp();

    // packed (w,w) weights (warp-uniform -> UR promotion)
    u64 wp[25];
    #pragma unroll
    for (int i = 0; i < 25; i++) { const float wv = __ldg(&Kw[i]); wp[i] = pk(wv, wv); }

    u64 acc[5][4];
    #pragma unroll
    for (int j = 0; j < 5; j++)
        #pragma unroll
        for (int q = 0; q < 4; q++) acc[j][q] = 0ull;   // slots start via mul anyway

    u64 p[11];

// Issue async fill of row ROWI into ring slot SLOT; always ends with a
// commit_group (possibly empty) so group counting stays uniform.
// Row covers global x = x0w-4 .. x0w+259 (66 x 16B chunks); the one
// permanently-OOB edge chunk is skipped (pre-zeroed above).
#define ISSUE_ROW(ROWI, SLOT) do {                                             \
    const int row_ = (ROWI);                                                   \
    if (row_ < NSTEP) {                                                        \
        const int gy_ = Y0 - 2 + row_;                                         \
        const unsigned sb_ = sbase + (SLOT) * ROWB;                            \
        if ((unsigned)gy_ < (unsigned)IMG) {                                   \
            const char* gs_ = (const char*)(Xc + (size_t)gy_ * IMG + x0w - 4); \
            if ((lane | warpX) != 0)                                           \
                cpa16(sb_ + lane * 16, gs_ + lane * 16);                       \
            cpa16(sb_ + (32 + lane) * 16, gs_ + (32 + lane) * 16);             \
            if (lane + warpX < 2)                                              \
                cpa16(sb_ + (64 + lane) * 16, gs_ + (64 + lane) * 16);         \
        } else {                                                               \
            stsz(sb_ + lane * 16);                                             \
            stsz(sb_ + (32 + lane) * 16);                                      \
            if (lane < 2) stsz(sb_ + (64 + lane) * 16);                        \
        }                                                                      \
    }                                                                          \
    asm volatile("cp.async.commit_group;");                                    \
} while (0)

// Read ring slot SLOT and pack p[0..10]. Lane window v[-2..9] = bytes
// lane*32+8 .. +55. Even pairs = aligned load results (no MOVs).
#define READPACK(SLOT) do {                                                    \
    const char* b_ = wring + (SLOT) * ROWB + lane * 32;                        \
    const float2 h0 = *reinterpret_cast<const float2*>(b_ + 8);                \
    const float4 A  = *reinterpret_cast<const float4*>(b_ + 16);               \
    const float4 B  = *reinterpret_cast<const float4*>(b_ + 32);               \
    const float2 h1 = *reinterpret_cast<const float2*>(b_ + 48);               \
    p[0]  = pk2(h0);                                                           \
    p[1]  = pk(h0.y, A.x);                                                     \
    p[2]  = pk(A.x,  A.y);                                                     \
    p[3]  = pk(A.y,  A.z);                                                     \
    p[4]  = pk(A.z,  A.w);                                                     \
    p[5]  = pk(A.w,  B.x);                                                     \
    p[6]  = pk(B.x,  B.y);                                                     \
    p[7]  = pk(B.y,  B.z);                                                     \
    p[8]  = pk(B.z,  B.w);                                                     \
    p[9]  = pk(B.w,  h1.x);                                                    \
    p[10] = pk2(h1);                                                           \
} while (0)

#define STORE_ROW(S) do {                                                      \
    float* op_ = Oc + (size_t)(Y0 + (S) - 4) * IMG + x0;                       \
    stg_cs(op_,     acc[((S)+1)%5][0], acc[((S)+1)%5][1]);                     \
    stg_cs(op_ + 4, acc[((S)+1)%5][2], acc[((S)+1)%5][3]);                     \
} while (0)

// Generic step with literal S and kr-range: issue row S+4 (depth-4), wait,
// read+pack row S, accumulate only useful kernel rows, store output S-4.
#define PSTEP(S, KRLO, KRHI) do {                                              \
    ISSUE_ROW((S) + 4, ((S) + 4) % 5);                                         \
    asm volatile("cp.async.wait_group 4;");                                    \
    __syncwarp();                                                              \
    READPACK((S) % 5);                                                         \
    accstep<(S) % 5, KRLO, KRHI>(acc, wp, p);                                  \
    if ((S) >= 4) STORE_ROW(S);                                                \
} while (0)

// Loop step: s = sb + J, sb % 5 == 4 -> all mod-5 indices are literals of J.
#define LSTEP(J) do {                                                          \
    const int s_ = sb + (J);                                                   \
    ISSUE_ROW(s_ + 4, ((J) + 3) % 5);                                          \
    asm volatile("cp.async.wait_group 4;");                                    \
    __syncwarp();                                                              \
    READPACK(((J) + 4) % 5);                                                   \
    accstep<((J) + 4) % 5, 0, 4>(acc, wp, p);                                  \
    {                                                                          \
        float* op_ = Oc + (size_t)(Y0 + s_ - 4) * IMG + x0;                    \
        stg_cs(op_,     acc[(J)%5][0], acc[(J)%5][1]);                         \
        stg_cs(op_ + 4, acc[(J)%5][2], acc[(J)%5][3]);                         \
    }                                                                          \
} while (0)

    // prologue: issue rows 0..3 (4 groups in flight)
    ISSUE_ROW(0, 0);
    ISSUE_ROW(1, 1);
    ISSUE_ROW(2, 2);
    ISSUE_ROW(3, 3);

    // warm-up steps 0..3: only kr <= s feeds real outputs
    PSTEP(0, 0, 0);
    PSTEP(1, 0, 1);
    PSTEP(2, 0, 2);
    PSTEP(3, 0, 3);

    // full steps 4..13 (two 5-blocks; sb = 4, 9)
    #pragma unroll 1
    for (int sb = 4; sb < 14; sb += 5) {
        LSTEP(0); LSTEP(1); LSTEP(2); LSTEP(3); LSTEP(4);
    }

    // full steps 14, 15
    PSTEP(14, 0, 4);
    PSTEP(15, 0, 4);

    // drain steps 16..19: only kr >= s-15 feeds real outputs
    PSTEP(16, 1, 4);
    PSTEP(17, 2, 4);
    PSTEP(18, 3, 4);
    PSTEP(19, 4, 4);

#undef LSTEP
#undef PSTEP
#undef STORE_ROW
#undef READPACK
#undef ISSUE_ROW
}

extern "C" void kernel_launch(void* const* d_in, const int* in_sizes, int n_in,
                              void* d_out, int out_size)
{
    const float* X  = (const float*)d_in[0];
    const float* Kw = (const float*)d_in[1];
    float* Out      = (float*)d_out;

    dim3 grid(2, IMG / R / 2, 128);   // 2 x-halves, 16 strip-pairs, 128 planes = 4096 CTAs
    dim3 block(32, 2);                // 2 warps, each owns one 256x16 strip
    conv5x5_kernel<<<grid, block>>>(X, Kw, Out);
}